// round 4
// baseline (speedup 1.0000x reference)
#include <cuda_runtime.h>
#include <cuda_bf16.h>
#include <stdint.h>

#define BZ 4
#define LL 1024
#define SS 8
#define KH 128
#define EE 512
#define PRIME 2147483647u
#define EMPTYV 0xffffffffu

// ---------------- device scratch ----------------
__device__ __align__(16) unsigned int  g_sig[2 * BZ * LL * KH];
__device__ __align__(16) unsigned int  g_sigT[2 * BZ * KH * LL];
__device__ __align__(16) int           g_cnti[BZ * LL * LL];
__device__ float         g_lut[129];
__device__ int           g_is64;
__device__ __align__(16) float         g_Mpart[4 * EE * EE];
__device__ __align__(16) float         g_M[EE * EE];        // M2 [e2][e1] fp32
__device__ __align__(16) float         g_u[BZ * LL * EE];   // u fp32 [b][r][e2]
__device__ __align__(16) float         g_vsumP[16 * BZ * EE];
__device__ __align__(16) float         g_vsum[BZ * EE];
__device__ __align__(16) float         g_usum[BZ * EE];
__device__ __align__(16) float         g_cvec[EE];
__device__ float         g_rowinv[BZ * LL];
__device__ int           g_nzc[BZ * LL];
__device__ __align__(16) int           g_nzi[BZ * LL * LL];
__device__ __align__(16) float         g_nzw[BZ * LL * LL];

// ---------------- f32x2 helpers (base sm_100-family PTX, no 'a' needed) -------
__device__ __forceinline__ unsigned long long pk_dup(float x) {
    unsigned long long d;
    unsigned u = __float_as_uint(x);
    asm("mov.b64 %0, {%1, %1};" : "=l"(d) : "r"(u));
    return d;
}
__device__ __forceinline__ unsigned long long pk_ab(float x, float y) {
    unsigned long long d;
    asm("mov.b64 %0, {%1, %2};" : "=l"(d) : "r"(__float_as_uint(x)), "r"(__float_as_uint(y)));
    return d;
}
__device__ __forceinline__ void ffma2(unsigned long long& d, unsigned long long a,
                                      unsigned long long b) {
    asm("fma.rn.f32x2 %0, %1, %2, %0;" : "+l"(d) : "l"(a), "l"(b));
}
__device__ __forceinline__ float2 up2(unsigned long long d) {
    unsigned lo, hi;
    asm("mov.b64 {%0, %1}, %2;" : "=r"(lo), "=r"(hi) : "l"(d));
    return make_float2(__uint_as_float(lo), __uint_as_float(hi));
}

// ---------------- init: dtype detect + LUT ----------------
__global__ void init_kernel(const void* ha) {
    int t = threadIdx.x;
    if (t == 0) {
        const int* p = (const int*)ha;
        int is64 = 1;
        for (int i = 0; i < 16; i++)
            if (p[2 * i + 1] != 0) is64 = 0;
        g_is64 = is64;
    }
    if (t < 129) {
        float j = (float)t / 128.0f;
        float delta = 16.0f * (1.0f - j) / (1.0f + j);
        float s = expf(-0.3f * delta);
        g_lut[t] = expf(s);
    }
}

// ---------------- MinHash sketches ----------------
__global__ __launch_bounds__(128) void sketch_kernel(const void* tsq, const void* tsk,
                                                     const void* ha, const void* hb) {
    __shared__ long long ids[SS];
    int row = blockIdx.x;
    int k = threadIdx.x;
    int is64 = g_is64;
    const void* ts = (row < BZ * LL) ? tsq : tsk;
    int r = row & (BZ * LL - 1);
    if (k < SS) {
        ids[k] = is64 ? ((const long long*)ts)[r * SS + k]
                      : (long long)((const int*)ts)[r * SS + k];
    }
    __syncthreads();
    unsigned int mn = 0xffffffffu;
    if (is64) {
        unsigned long long a = (unsigned long long)((const long long*)ha)[k];
        unsigned long long b = (unsigned long long)((const long long*)hb)[k];
        #pragma unroll
        for (int s = 0; s < SS; s++) {
            unsigned long long x = (unsigned long long)ids[s] * a + b;
            unsigned long long t = (x >> 31) + (x & 0x7fffffffULL);
            t = (t >> 31) + (t & 0x7fffffffULL);
            if (t >= 0x7fffffffULL) t -= 0x7fffffffULL;
            unsigned int v = (unsigned int)t;
            if (v < mn) mn = v;
        }
    } else {
        unsigned int a = (unsigned int)((const int*)ha)[k];
        unsigned int b = (unsigned int)((const int*)hb)[k];
        #pragma unroll
        for (int s = 0; s < SS; s++) {
            unsigned int xu = (unsigned int)((long long)ids[s]) * a + b;
            int x = (int)xu;
            long long m = (long long)x % (long long)PRIME;
            if (m < 0) m += (long long)PRIME;
            unsigned int v = (unsigned int)m;
            if (v < mn) mn = v;
        }
    }
    g_sig[row * KH + k] = mn;
}

// ---------------- signature transpose ----------------
__global__ void sigT_kernel() {
    __shared__ unsigned int t[32][33];
    int z = blockIdx.z;
    int x0 = blockIdx.x * 32, y0 = blockIdx.y * 32;
    int tx = threadIdx.x, ty = threadIdx.y;
    #pragma unroll
    for (int i = 0; i < 32; i += 8)
        t[ty + i][tx] = g_sig[(z * LL + y0 + ty + i) * KH + x0 + tx];
    __syncthreads();
    #pragma unroll
    for (int i = 0; i < 32; i += 8)
        g_sigT[(z * KH + x0 + ty + i) * LL + y0 + tx] = t[tx][ty + i];
}

// ---------------- M2 GEMM (NN): C[e2][e1] = sum_o Wo[e2][o]*Wv[o][e1], splitK=4 -
__global__ __launch_bounds__(256) void gemm_M2_kernel(const float* __restrict__ Wo,
                                                      const float* __restrict__ Wv) {
    __shared__ float As[16][68];
    __shared__ float Bs[16][68];
    int tid = threadIdx.x;
    int mi = tid & 15, ni = tid >> 4;
    int i0 = blockIdx.x * 64, j0 = blockIdx.y * 64;
    int kz = blockIdx.z;
    float acc[4][4] = {};
    for (int k0 = kz * 128; k0 < kz * 128 + 128; k0 += 16) {
        {   // A: 64 rows(e2) x 16 k, transpose scatter
            int ar = tid >> 2, ac = tid & 3;
            float4 v = *(const float4*)&Wo[(size_t)(i0 + ar) * EE + k0 + ac * 4];
            As[ac * 4 + 0][ar] = v.x; As[ac * 4 + 1][ar] = v.y;
            As[ac * 4 + 2][ar] = v.z; As[ac * 4 + 3][ar] = v.w;
        }
        {   // B: 16 rows(o=k) x 64 cols(e1), direct
            int kk = tid >> 4, jseg = tid & 15;
            *(float4*)&Bs[kk][jseg * 4] =
                *(const float4*)&Wv[(size_t)(k0 + kk) * EE + j0 + jseg * 4];
        }
        __syncthreads();
        #pragma unroll
        for (int k = 0; k < 16; k++) {
            float4 a4 = *(float4*)&As[k][mi * 4];
            float4 b4 = *(float4*)&Bs[k][ni * 4];
            float a[4] = {a4.x, a4.y, a4.z, a4.w};
            float bb[4] = {b4.x, b4.y, b4.z, b4.w};
            #pragma unroll
            for (int r = 0; r < 4; r++)
                #pragma unroll
                for (int c = 0; c < 4; c++)
                    acc[r][c] += a[r] * bb[c];
        }
        __syncthreads();
    }
    float* outp = g_Mpart + (size_t)kz * EE * EE;
    #pragma unroll
    for (int r = 0; r < 4; r++) {
        float4 o = make_float4(acc[r][0], acc[r][1], acc[r][2], acc[r][3]);
        *(float4*)&outp[(size_t)(i0 + mi * 4 + r) * EE + j0 + ni * 4] = o;
    }
}

__global__ void reduceM_kernel() {
    int idx = blockIdx.x * 256 + threadIdx.x;
    g_M[idx] = g_Mpart[idx] + g_Mpart[idx + EE * EE]
             + g_Mpart[idx + 2 * EE * EE] + g_Mpart[idx + 3 * EE * EE];
}

// ---------------- dense-term chain ----------------
__global__ __launch_bounds__(256) void vsum1_kernel(const float* __restrict__ value) {
    int b = blockIdx.y, lc = blockIdx.x;
    const float* vp = value + ((size_t)b * LL + lc * 64) * EE;
    int e = threadIdx.x;
    float a0 = 0.f, a1 = 0.f;
    for (int r = 0; r < 64; r++) {
        a0 += vp[(size_t)r * EE + e];
        a1 += vp[(size_t)r * EE + e + 256];
    }
    g_vsumP[(size_t)(b * 16 + lc) * EE + e] = a0;
    g_vsumP[(size_t)(b * 16 + lc) * EE + e + 256] = a1;
}
__global__ void vsum2_kernel() {
    int b = blockIdx.y;
    int e = blockIdx.x * 128 + threadIdx.x;
    float s = 0.f;
    for (int c = 0; c < 16; c++) s += g_vsumP[(size_t)(b * 16 + c) * EE + e];
    g_vsum[b * EE + e] = s;
}
__global__ __launch_bounds__(256) void usum_kernel() {
    int b = blockIdx.y;
    int e2 = blockIdx.x * 8 + (threadIdx.x >> 5);
    int lane = threadIdx.x & 31;
    const float* mr = g_M + (size_t)e2 * EE;
    const float* vs = g_vsum + b * EE;
    float s = 0.f;
    for (int i = lane; i < EE; i += 32) s += mr[i] * vs[i];
    #pragma unroll
    for (int o = 16; o; o >>= 1) s += __shfl_xor_sync(0xffffffffu, s, o);
    if (lane == 0) g_usum[b * EE + e2] = s;
}
__global__ __launch_bounds__(256) void cvec_kernel(const float* __restrict__ Wo,
                                                   const float* __restrict__ bv,
                                                   const float* __restrict__ bo) {
    int e2 = blockIdx.x * 8 + (threadIdx.x >> 5);
    int lane = threadIdx.x & 31;
    const float* wr = Wo + (size_t)e2 * EE;
    float s = 0.f;
    for (int i = lane; i < EE; i += 32) s += wr[i] * bv[i];
    #pragma unroll
    for (int o = 16; o; o >>= 1) s += __shfl_xor_sync(0xffffffffu, s, o);
    if (lane == 0) g_cvec[e2] = s + bo[e2];
}

// ---------------- u GEMM (f32x2): u[r][e2] = sum_e1 value[r][e1]*M2[e2][e1] -----
// BM=BN=128, BK=16, 256 threads, 8x8 fragment split 4+4 (stride 64)
__global__ __launch_bounds__(256) void gemm_u_kernel(const float* __restrict__ value) {
    __shared__ float As[16][132];
    __shared__ float Bs[16][132];
    int tid = threadIdx.x;
    int mi = tid & 15, ni = tid >> 4;
    int rt = blockIdx.x;
    int b = rt >> 3;
    int i0 = (rt & 7) * 128;
    int j0 = blockIdx.y * 128;
    const float* A = value + ((size_t)(b * LL) + i0) * EE;
    const float* B = g_M + (size_t)j0 * EE;

    unsigned long long acc[2][2][2][4];  // [rh][rp][ch][cc]
    #pragma unroll
    for (int rh = 0; rh < 2; rh++)
        #pragma unroll
        for (int rp = 0; rp < 2; rp++)
            #pragma unroll
            for (int ch = 0; ch < 2; ch++)
                #pragma unroll
                for (int cc = 0; cc < 4; cc++)
                    acc[rh][rp][ch][cc] = 0ULL;

    int sr = tid >> 2, sc = tid & 3;
    float4 pa0, pa1, pb0, pb1;
    // prefetch tile 0
    pa0 = *(const float4*)(A + (size_t)sr * EE + sc * 4);
    pa1 = *(const float4*)(A + (size_t)(sr + 64) * EE + sc * 4);
    pb0 = *(const float4*)(B + (size_t)sr * EE + sc * 4);
    pb1 = *(const float4*)(B + (size_t)(sr + 64) * EE + sc * 4);

    for (int t = 0; t < 32; t++) {
        // stage to smem (k-transposed)
        As[sc * 4 + 0][sr] = pa0.x; As[sc * 4 + 1][sr] = pa0.y;
        As[sc * 4 + 2][sr] = pa0.z; As[sc * 4 + 3][sr] = pa0.w;
        As[sc * 4 + 0][sr + 64] = pa1.x; As[sc * 4 + 1][sr + 64] = pa1.y;
        As[sc * 4 + 2][sr + 64] = pa1.z; As[sc * 4 + 3][sr + 64] = pa1.w;
        Bs[sc * 4 + 0][sr] = pb0.x; Bs[sc * 4 + 1][sr] = pb0.y;
        Bs[sc * 4 + 2][sr] = pb0.z; Bs[sc * 4 + 3][sr] = pb0.w;
        Bs[sc * 4 + 0][sr + 64] = pb1.x; Bs[sc * 4 + 1][sr + 64] = pb1.y;
        Bs[sc * 4 + 2][sr + 64] = pb1.z; Bs[sc * 4 + 3][sr + 64] = pb1.w;
        __syncthreads();
        if (t < 31) {
            int k0 = (t + 1) * 16;
            pa0 = *(const float4*)(A + (size_t)sr * EE + k0 + sc * 4);
            pa1 = *(const float4*)(A + (size_t)(sr + 64) * EE + k0 + sc * 4);
            pb0 = *(const float4*)(B + (size_t)sr * EE + k0 + sc * 4);
            pb1 = *(const float4*)(B + (size_t)(sr + 64) * EE + k0 + sc * 4);
        }
        #pragma unroll
        for (int kk = 0; kk < 16; kk++) {
            float4 a0 = *(float4*)&As[kk][mi * 4];
            float4 a1 = *(float4*)&As[kk][64 + mi * 4];
            float4 b0 = *(float4*)&Bs[kk][ni * 4];
            float4 b1 = *(float4*)&Bs[kk][64 + ni * 4];
            unsigned long long pa[2][2], pb[2][4];
            pa[0][0] = pk_ab(a0.x, a0.y); pa[0][1] = pk_ab(a0.z, a0.w);
            pa[1][0] = pk_ab(a1.x, a1.y); pa[1][1] = pk_ab(a1.z, a1.w);
            pb[0][0] = pk_dup(b0.x); pb[0][1] = pk_dup(b0.y);
            pb[0][2] = pk_dup(b0.z); pb[0][3] = pk_dup(b0.w);
            pb[1][0] = pk_dup(b1.x); pb[1][1] = pk_dup(b1.y);
            pb[1][2] = pk_dup(b1.z); pb[1][3] = pk_dup(b1.w);
            #pragma unroll
            for (int rh = 0; rh < 2; rh++)
                #pragma unroll
                for (int rp = 0; rp < 2; rp++)
                    #pragma unroll
                    for (int ch = 0; ch < 2; ch++)
                        #pragma unroll
                        for (int cc = 0; cc < 4; cc++)
                            ffma2(acc[rh][rp][ch][cc], pa[rh][rp], pb[ch][cc]);
        }
        __syncthreads();
    }

    // epilogue: rows i0 + rh*64 + mi*4 + 2rp + h ; cols j0 + ch*64 + ni*4 + cc
    #pragma unroll
    for (int rh = 0; rh < 2; rh++)
        #pragma unroll
        for (int rp = 0; rp < 2; rp++)
            #pragma unroll
            for (int h = 0; h < 2; h++) {
                int row = i0 + rh * 64 + mi * 4 + 2 * rp + h;
                float* orow = g_u + ((size_t)(b * LL) + row) * EE + j0;
                #pragma unroll
                for (int ch = 0; ch < 2; ch++) {
                    float2 v0 = up2(acc[rh][rp][ch][0]);
                    float2 v1 = up2(acc[rh][rp][ch][1]);
                    float2 v2 = up2(acc[rh][rp][ch][2]);
                    float2 v3 = up2(acc[rh][rp][ch][3]);
                    float4 o = h ? make_float4(v0.y, v1.y, v2.y, v3.y)
                                 : make_float4(v0.x, v1.x, v2.x, v3.x);
                    *(float4*)(orow + ch * 64 + ni * 4) = o;
                }
            }
}

// ---------------- zero counts ----------------
__global__ void zero_kernel() {
    int idx = blockIdx.x * 256 + threadIdx.x;
    ((int4*)g_cnti)[idx] = make_int4(0, 0, 0, 0);
}

// ---------------- hash join per (slot, batch) ----------------
__global__ __launch_bounds__(256) void hashjoin_kernel() {
    __shared__ unsigned int tval[2048];
    __shared__ int          trow[2048];
    int k = blockIdx.x, b = blockIdx.y;
    int tid = threadIdx.x;
    for (int i = tid; i < 2048; i += 256) tval[i] = EMPTYV;
    __syncthreads();
    const unsigned* SK = g_sigT + ((size_t)((1 * BZ + b) * KH + k)) * LL;
    const unsigned* SQ = g_sigT + ((size_t)((0 * BZ + b) * KH + k)) * LL;
    for (int j = tid; j < LL; j += 256) {
        unsigned v = SK[j];
        int slot = (int)((v * 2654435761u) >> 20) & 2047;
        while (true) {
            unsigned old = atomicCAS(&tval[slot], EMPTYV, v);
            if (old == EMPTYV) { trow[slot] = j; break; }
            slot = (slot + 1) & 2047;
        }
    }
    __syncthreads();
    int* cb = g_cnti + (size_t)b * LL * LL;
    for (int i = tid; i < LL; i += 256) {
        unsigned v = SQ[i];
        int slot = (int)((v * 2654435761u) >> 20) & 2047;
        while (tval[slot] != EMPTYV) {
            if (tval[slot] == v)
                atomicAdd(&cb[(size_t)i * LL + trow[slot]], 1);
            slot = (slot + 1) & 2047;
        }
    }
}

// ---------------- sparse lists + softmax denom ----------------
__global__ __launch_bounds__(256) void build_sparse_kernel() {
    int row = blockIdx.x * 8 + (threadIdx.x >> 5);
    int lane = threadIdx.x & 31;
    const int* cr = g_cnti + (size_t)row * LL;
    float lut0 = g_lut[0];
    float rsum = 0.f;
    int base = 0;
    int* oi = g_nzi + (size_t)row * LL;
    float* ow = g_nzw + (size_t)row * LL;
    for (int c = 0; c < 32; c++) {
        int j = c * 32 + lane;
        int m = cr[j];
        rsum += g_lut[m];
        unsigned mask = __ballot_sync(0xffffffffu, m != 0);
        if (m) {
            int pos = base + __popc(mask & ((1u << lane) - 1u));
            oi[pos] = j;
            ow[pos] = g_lut[m] - lut0;
        }
        base += __popc(mask);
    }
    #pragma unroll
    for (int o = 16; o; o >>= 1) rsum += __shfl_xor_sync(0xffffffffu, rsum, o);
    if (lane == 0) {
        g_nzc[row] = base;
        g_rowinv[row] = 1.0f / rsum;
    }
}

// ---------------- output ----------------
__global__ __launch_bounds__(128) void out_kernel(float* __restrict__ out) {
    int row = blockIdx.x;
    int b = row >> 10;
    int e4 = threadIdx.x;
    float lut0 = g_lut[0];
    float4 us = ((const float4*)g_usum)[b * 128 + e4];
    float4 acc = make_float4(us.x * lut0, us.y * lut0, us.z * lut0, us.w * lut0);
    int n = g_nzc[row];
    const int* oi = g_nzi + (size_t)row * LL;
    const float* ow = g_nzw + (size_t)row * LL;
    const float4* ub = (const float4*)g_u + (size_t)b * LL * 128;
    for (int t = 0; t < n; t++) {
        int j = oi[t];
        float w = ow[t];
        float4 u4 = ub[(size_t)j * 128 + e4];
        acc.x += w * u4.x; acc.y += w * u4.y;
        acc.z += w * u4.z; acc.w += w * u4.w;
    }
    float inv = g_rowinv[row];
    float4 cc = ((const float4*)g_cvec)[e4];
    float4 o = make_float4(acc.x * inv + cc.x, acc.y * inv + cc.y,
                           acc.z * inv + cc.z, acc.w * inv + cc.w);
    ((float4*)out)[(size_t)row * 128 + e4] = o;
}

// ---------------- launch ----------------
extern "C" void kernel_launch(void* const* d_in, const int* in_sizes, int n_in,
                              void* d_out, int out_size) {
    const float* value = (const float*)d_in[2];
    const void*  tsq   = d_in[3];
    const void*  tsk   = d_in[4];
    const void*  ha    = d_in[5];
    const void*  hb    = d_in[6];
    const float* Wv    = (const float*)d_in[11];
    const float* bv    = (const float*)d_in[12];
    const float* Wo    = (const float*)d_in[13];
    const float* bo    = (const float*)d_in[14];
    float* out = (float*)d_out;

    init_kernel<<<1, 160>>>(ha);                                        // 0
    sketch_kernel<<<2 * BZ * LL, 128>>>(tsq, tsk, ha, hb);              // 1
    sigT_kernel<<<dim3(KH / 32, LL / 32, 2 * BZ), dim3(32, 8)>>>();     // 2
    zero_kernel<<<BZ * LL * LL / 4 / 256, 256>>>();                     // 3
    gemm_M2_kernel<<<dim3(8, 8, 4), 256>>>(Wo, Wv);                     // 4
    hashjoin_kernel<<<dim3(KH, BZ), 256>>>();                           // 5  <- profiled
    reduceM_kernel<<<EE * EE / 256, 256>>>();                           // 6
    vsum1_kernel<<<dim3(16, BZ), 256>>>(value);                         // 7
    vsum2_kernel<<<dim3(EE / 128, BZ), 128>>>();                        // 8
    usum_kernel<<<dim3(EE / 8, BZ), 256>>>();                           // 9
    cvec_kernel<<<EE / 8, 256>>>(Wo, bv, bo);                           // 10
    gemm_u_kernel<<<dim3(BZ * LL / 128, EE / 128), 256>>>(value);       // 11
    build_sparse_kernel<<<BZ * LL / 8, 256>>>();                        // 12
    out_kernel<<<BZ * LL, 128>>>(out);                                  // 13
}

// round 5
// speedup vs baseline: 1.5760x; 1.5760x over previous
#include <cuda_runtime.h>
#include <cuda_bf16.h>
#include <stdint.h>

#define BZ 4
#define LL 1024
#define SS 8
#define KH 128
#define EE 512
#define PRIME 2147483647u
#define EMPTYV 0xffffffffu
#define EVCAP 256

// ---------------- device scratch ----------------
__device__ __align__(16) unsigned int  g_sig[2 * BZ * LL * KH];
__device__ __align__(16) unsigned int  g_sigT[2 * BZ * KH * LL];
__device__ float         g_lut[129];
__device__ int           g_is64;
__device__ __align__(16) float         g_Mpart[4 * EE * EE];
__device__ __align__(16) float         g_M[EE * EE];        // M2 [e2][e1] fp32
__device__ __align__(16) float         g_u[BZ * LL * EE];   // u fp32 [b][r][e2]
__device__ __align__(16) float         g_vsumP[16 * BZ * EE];
__device__ __align__(16) float         g_vsum[BZ * EE];
__device__ __align__(16) float         g_usum[BZ * EE];
__device__ __align__(16) float         g_cvec[EE];
__device__ float         g_rowinv[BZ * LL];
__device__ int           g_evc[BZ * LL];                    // event counters
__device__ __align__(16) int           g_evj[BZ * LL * EVCAP];  // event j lists (4MB)
__device__ int           g_nzc[BZ * LL];
__device__ __align__(16) int           g_nzi[BZ * LL * EVCAP];
__device__ __align__(16) float         g_nzw[BZ * LL * EVCAP];

// ---------------- f32x2 helpers ----------------
__device__ __forceinline__ unsigned long long pk_dup(float x) {
    unsigned long long d;
    unsigned u = __float_as_uint(x);
    asm("mov.b64 %0, {%1, %1};" : "=l"(d) : "r"(u));
    return d;
}
__device__ __forceinline__ unsigned long long pk_ab(float x, float y) {
    unsigned long long d;
    asm("mov.b64 %0, {%1, %2};" : "=l"(d) : "r"(__float_as_uint(x)), "r"(__float_as_uint(y)));
    return d;
}
__device__ __forceinline__ void ffma2(unsigned long long& d, unsigned long long a,
                                      unsigned long long b) {
    asm("fma.rn.f32x2 %0, %1, %2, %0;" : "+l"(d) : "l"(a), "l"(b));
}
__device__ __forceinline__ float2 up2(unsigned long long d) {
    unsigned lo, hi;
    asm("mov.b64 {%0, %1}, %2;" : "=r"(lo), "=r"(hi) : "l"(d));
    return make_float2(__uint_as_float(lo), __uint_as_float(hi));
}

// ---------------- init: dtype detect + LUT + zero event counters ----------------
__global__ void init_kernel(const void* ha) {
    if (blockIdx.x > 0) {
        g_evc[(blockIdx.x - 1) * 256 + threadIdx.x] = 0;
        return;
    }
    int t = threadIdx.x;
    if (t == 0) {
        const int* p = (const int*)ha;
        int is64 = 1;
        for (int i = 0; i < 16; i++)
            if (p[2 * i + 1] != 0) is64 = 0;
        g_is64 = is64;
    }
    if (t < 129) {
        float j = (float)t / 128.0f;
        float delta = 16.0f * (1.0f - j) / (1.0f + j);
        float s = expf(-0.3f * delta);
        g_lut[t] = expf(s);
    }
}

// ---------------- MinHash sketches (u32 mul.wide + single Mersenne fold) -------
__global__ __launch_bounds__(128) void sketch_kernel(const void* tsq, const void* tsk,
                                                     const void* ha, const void* hb) {
    __shared__ unsigned ids[SS];
    int row = blockIdx.x;
    int k = threadIdx.x;
    int is64 = g_is64;
    const void* ts = (row < BZ * LL) ? tsq : tsk;
    int r = row & (BZ * LL - 1);
    if (k < SS) {
        // ids are in [0, 32000): low 32 bits hold the value in both storages
        ids[k] = is64 ? ((const unsigned*)ts)[(r * SS + k) * 2]
                      : ((const unsigned*)ts)[r * SS + k];
    }
    __syncthreads();
    unsigned mn = 0xffffffffu;
    if (is64) {
        unsigned a = ((const unsigned*)ha)[2 * k];   // < PRIME, high word 0
        unsigned b = ((const unsigned*)hb)[2 * k];
        #pragma unroll
        for (int s = 0; s < SS; s++) {
            unsigned long long x = (unsigned long long)ids[s] * a + b;   // < 2^46
            unsigned t = (unsigned)(x >> 31) + ((unsigned)x & 0x7fffffffu);
            t = (t >= PRIME) ? t - PRIME : t;      // exact: hi<2^15 -> one sub
            mn = min(mn, t);
        }
    } else {
        unsigned a = ((const unsigned*)ha)[k];
        unsigned b = ((const unsigned*)hb)[k];
        #pragma unroll
        for (int s = 0; s < SS; s++) {
            unsigned xu = ids[s] * a + b;           // wraps mod 2^32
            int x = (int)xu;
            long long m = (long long)x % (long long)PRIME;
            if (m < 0) m += (long long)PRIME;
            mn = min(mn, (unsigned)m);
        }
    }
    g_sig[row * KH + k] = mn;
}

// ---------------- signature transpose ----------------
__global__ void sigT_kernel() {
    __shared__ unsigned int t[32][33];
    int z = blockIdx.z;
    int x0 = blockIdx.x * 32, y0 = blockIdx.y * 32;
    int tx = threadIdx.x, ty = threadIdx.y;
    #pragma unroll
    for (int i = 0; i < 32; i += 8)
        t[ty + i][tx] = g_sig[(z * LL + y0 + ty + i) * KH + x0 + tx];
    __syncthreads();
    #pragma unroll
    for (int i = 0; i < 32; i += 8)
        g_sigT[(z * KH + x0 + ty + i) * LL + y0 + tx] = t[tx][ty + i];
}

// ---------------- M2 GEMM (NN), splitK=4 ----------------
__global__ __launch_bounds__(256) void gemm_M2_kernel(const float* __restrict__ Wo,
                                                      const float* __restrict__ Wv) {
    __shared__ float As[16][68];
    __shared__ float Bs[16][68];
    int tid = threadIdx.x;
    int mi = tid & 15, ni = tid >> 4;
    int i0 = blockIdx.x * 64, j0 = blockIdx.y * 64;
    int kz = blockIdx.z;
    float acc[4][4] = {};
    for (int k0 = kz * 128; k0 < kz * 128 + 128; k0 += 16) {
        {
            int ar = tid >> 2, ac = tid & 3;
            float4 v = *(const float4*)&Wo[(size_t)(i0 + ar) * EE + k0 + ac * 4];
            As[ac * 4 + 0][ar] = v.x; As[ac * 4 + 1][ar] = v.y;
            As[ac * 4 + 2][ar] = v.z; As[ac * 4 + 3][ar] = v.w;
        }
        {
            int kk = tid >> 4, jseg = tid & 15;
            *(float4*)&Bs[kk][jseg * 4] =
                *(const float4*)&Wv[(size_t)(k0 + kk) * EE + j0 + jseg * 4];
        }
        __syncthreads();
        #pragma unroll
        for (int k = 0; k < 16; k++) {
            float4 a4 = *(float4*)&As[k][mi * 4];
            float4 b4 = *(float4*)&Bs[k][ni * 4];
            float a[4] = {a4.x, a4.y, a4.z, a4.w};
            float bb[4] = {b4.x, b4.y, b4.z, b4.w};
            #pragma unroll
            for (int r = 0; r < 4; r++)
                #pragma unroll
                for (int c = 0; c < 4; c++)
                    acc[r][c] += a[r] * bb[c];
        }
        __syncthreads();
    }
    float* outp = g_Mpart + (size_t)kz * EE * EE;
    #pragma unroll
    for (int r = 0; r < 4; r++) {
        float4 o = make_float4(acc[r][0], acc[r][1], acc[r][2], acc[r][3]);
        *(float4*)&outp[(size_t)(i0 + mi * 4 + r) * EE + j0 + ni * 4] = o;
    }
}

__global__ void reduceM_kernel() {
    int idx = blockIdx.x * 256 + threadIdx.x;
    g_M[idx] = g_Mpart[idx] + g_Mpart[idx + EE * EE]
             + g_Mpart[idx + 2 * EE * EE] + g_Mpart[idx + 3 * EE * EE];
}

// ---------------- u GEMM (f32x2) 128x128x16 tiles ----------------
__global__ __launch_bounds__(256) void gemm_u_kernel(const float* __restrict__ value) {
    __shared__ float As[16][132];
    __shared__ float Bs[16][132];
    int tid = threadIdx.x;
    int mi = tid & 15, ni = tid >> 4;
    int rt = blockIdx.x;
    int b = rt >> 3;
    int i0 = (rt & 7) * 128;
    int j0 = blockIdx.y * 128;
    const float* A = value + ((size_t)(b * LL) + i0) * EE;
    const float* B = g_M + (size_t)j0 * EE;

    unsigned long long acc[2][2][2][4];
    #pragma unroll
    for (int rh = 0; rh < 2; rh++)
        #pragma unroll
        for (int rp = 0; rp < 2; rp++)
            #pragma unroll
            for (int ch = 0; ch < 2; ch++)
                #pragma unroll
                for (int cc = 0; cc < 4; cc++)
                    acc[rh][rp][ch][cc] = 0ULL;

    int sr = tid >> 2, sc = tid & 3;
    float4 pa0, pa1, pb0, pb1;
    pa0 = *(const float4*)(A + (size_t)sr * EE + sc * 4);
    pa1 = *(const float4*)(A + (size_t)(sr + 64) * EE + sc * 4);
    pb0 = *(const float4*)(B + (size_t)sr * EE + sc * 4);
    pb1 = *(const float4*)(B + (size_t)(sr + 64) * EE + sc * 4);

    for (int t = 0; t < 32; t++) {
        As[sc * 4 + 0][sr] = pa0.x; As[sc * 4 + 1][sr] = pa0.y;
        As[sc * 4 + 2][sr] = pa0.z; As[sc * 4 + 3][sr] = pa0.w;
        As[sc * 4 + 0][sr + 64] = pa1.x; As[sc * 4 + 1][sr + 64] = pa1.y;
        As[sc * 4 + 2][sr + 64] = pa1.z; As[sc * 4 + 3][sr + 64] = pa1.w;
        Bs[sc * 4 + 0][sr] = pb0.x; Bs[sc * 4 + 1][sr] = pb0.y;
        Bs[sc * 4 + 2][sr] = pb0.z; Bs[sc * 4 + 3][sr] = pb0.w;
        Bs[sc * 4 + 0][sr + 64] = pb1.x; Bs[sc * 4 + 1][sr + 64] = pb1.y;
        Bs[sc * 4 + 2][sr + 64] = pb1.z; Bs[sc * 4 + 3][sr + 64] = pb1.w;
        __syncthreads();
        if (t < 31) {
            int k0 = (t + 1) * 16;
            pa0 = *(const float4*)(A + (size_t)sr * EE + k0 + sc * 4);
            pa1 = *(const float4*)(A + (size_t)(sr + 64) * EE + k0 + sc * 4);
            pb0 = *(const float4*)(B + (size_t)sr * EE + k0 + sc * 4);
            pb1 = *(const float4*)(B + (size_t)(sr + 64) * EE + k0 + sc * 4);
        }
        #pragma unroll
        for (int kk = 0; kk < 16; kk++) {
            float4 a0 = *(float4*)&As[kk][mi * 4];
            float4 a1 = *(float4*)&As[kk][64 + mi * 4];
            float4 b0 = *(float4*)&Bs[kk][ni * 4];
            float4 b1 = *(float4*)&Bs[kk][64 + ni * 4];
            unsigned long long pa[2][2], pb[2][4];
            pa[0][0] = pk_ab(a0.x, a0.y); pa[0][1] = pk_ab(a0.z, a0.w);
            pa[1][0] = pk_ab(a1.x, a1.y); pa[1][1] = pk_ab(a1.z, a1.w);
            pb[0][0] = pk_dup(b0.x); pb[0][1] = pk_dup(b0.y);
            pb[0][2] = pk_dup(b0.z); pb[0][3] = pk_dup(b0.w);
            pb[1][0] = pk_dup(b1.x); pb[1][1] = pk_dup(b1.y);
            pb[1][2] = pk_dup(b1.z); pb[1][3] = pk_dup(b1.w);
            #pragma unroll
            for (int rh = 0; rh < 2; rh++)
                #pragma unroll
                for (int rp = 0; rp < 2; rp++)
                    #pragma unroll
                    for (int ch = 0; ch < 2; ch++)
                        #pragma unroll
                        for (int cc = 0; cc < 4; cc++)
                            ffma2(acc[rh][rp][ch][cc], pa[rh][rp], pb[ch][cc]);
        }
        __syncthreads();
    }

    #pragma unroll
    for (int rh = 0; rh < 2; rh++)
        #pragma unroll
        for (int rp = 0; rp < 2; rp++)
            #pragma unroll
            for (int h = 0; h < 2; h++) {
                int row = i0 + rh * 64 + mi * 4 + 2 * rp + h;
                float* orow = g_u + ((size_t)(b * LL) + row) * EE + j0;
                #pragma unroll
                for (int ch = 0; ch < 2; ch++) {
                    float2 v0 = up2(acc[rh][rp][ch][0]);
                    float2 v1 = up2(acc[rh][rp][ch][1]);
                    float2 v2 = up2(acc[rh][rp][ch][2]);
                    float2 v3 = up2(acc[rh][rp][ch][3]);
                    float4 o = h ? make_float4(v0.y, v1.y, v2.y, v3.y)
                                 : make_float4(v0.x, v1.x, v2.x, v3.x);
                    *(float4*)(orow + ch * 64 + ni * 4) = o;
                }
            }
}

// ---------------- dense-term chain ----------------
__global__ __launch_bounds__(256) void vsum1_kernel(const float* __restrict__ value) {
    int b = blockIdx.y, lc = blockIdx.x;
    const float* vp = value + ((size_t)b * LL + lc * 64) * EE;
    int e = threadIdx.x;
    float a0 = 0.f, a1 = 0.f;
    for (int r = 0; r < 64; r++) {
        a0 += vp[(size_t)r * EE + e];
        a1 += vp[(size_t)r * EE + e + 256];
    }
    g_vsumP[(size_t)(b * 16 + lc) * EE + e] = a0;
    g_vsumP[(size_t)(b * 16 + lc) * EE + e + 256] = a1;
}
__global__ void vsum2_kernel() {
    int b = blockIdx.y;
    int e = blockIdx.x * 128 + threadIdx.x;
    float s = 0.f;
    for (int c = 0; c < 16; c++) s += g_vsumP[(size_t)(b * 16 + c) * EE + e];
    g_vsum[b * EE + e] = s;
}
__global__ __launch_bounds__(256) void usum_kernel() {
    int b = blockIdx.y;
    int e2 = blockIdx.x * 8 + (threadIdx.x >> 5);
    int lane = threadIdx.x & 31;
    const float* mr = g_M + (size_t)e2 * EE;
    const float* vs = g_vsum + b * EE;
    float s = 0.f;
    for (int i = lane; i < EE; i += 32) s += mr[i] * vs[i];
    #pragma unroll
    for (int o = 16; o; o >>= 1) s += __shfl_xor_sync(0xffffffffu, s, o);
    if (lane == 0) g_usum[b * EE + e2] = s;
}
__global__ __launch_bounds__(256) void cvec_kernel(const float* __restrict__ Wo,
                                                   const float* __restrict__ bv,
                                                   const float* __restrict__ bo) {
    int e2 = blockIdx.x * 8 + (threadIdx.x >> 5);
    int lane = threadIdx.x & 31;
    const float* wr = Wo + (size_t)e2 * EE;
    float s = 0.f;
    for (int i = lane; i < EE; i += 32) s += wr[i] * bv[i];
    #pragma unroll
    for (int o = 16; o; o >>= 1) s += __shfl_xor_sync(0xffffffffu, s, o);
    if (lane == 0) g_cvec[e2] = s + bo[e2];
}

// ---------------- hash join per (slot, batch): emit events ----------------
__global__ __launch_bounds__(256) void hashjoin_kernel() {
    __shared__ unsigned int tval[2048];
    __shared__ short        trow[2048];
    int k = blockIdx.x, b = blockIdx.y;
    int tid = threadIdx.x;
    for (int i = tid; i < 2048; i += 256) tval[i] = EMPTYV;
    __syncthreads();
    const unsigned* SK = g_sigT + ((size_t)((1 * BZ + b) * KH + k)) * LL;
    const unsigned* SQ = g_sigT + ((size_t)((0 * BZ + b) * KH + k)) * LL;
    for (int j = tid; j < LL; j += 256) {
        unsigned v = SK[j];
        int slot = (int)((v * 2654435761u) >> 20) & 2047;
        while (true) {
            unsigned old = atomicCAS(&tval[slot], EMPTYV, v);
            if (old == EMPTYV) { trow[slot] = (short)j; break; }
            slot = (slot + 1) & 2047;
        }
    }
    __syncthreads();
    for (int i = tid; i < LL; i += 256) {
        unsigned v = SQ[i];
        int slot = (int)((v * 2654435761u) >> 20) & 2047;
        while (tval[slot] != EMPTYV) {
            if (tval[slot] == v) {
                int row = b * LL + i;
                int pos = atomicAdd(&g_evc[row], 1);
                if (pos < EVCAP) g_evj[(size_t)row * EVCAP + pos] = trow[slot];
            }
            slot = (slot + 1) & 2047;
        }
    }
}

// ---------------- per-row: sort events, aggregate runs, denom ----------------
// warp per row; deterministic (sorted by j)
__global__ __launch_bounds__(256) void build_sparse_kernel() {
    __shared__ int buf[8][EVCAP];
    int w = threadIdx.x >> 5;
    int lane = threadIdx.x & 31;
    int row = blockIdx.x * 8 + w;
    int n = g_evc[row];
    if (n > EVCAP) n = EVCAP;
    int* bw = buf[w];
    for (int p = lane; p < EVCAP; p += 32)
        bw[p] = (p < n) ? g_evj[(size_t)row * EVCAP + p] : 0x7fffffff;
    __syncwarp();
    // odd-even transposition sort: n passes over first n elements
    for (int pass = 0; pass < n; pass++) {
        int start = pass & 1;
        for (int p = start + lane * 2; p + 1 < n; p += 64) {
            int a = bw[p], c = bw[p + 1];
            if (c < a) { bw[p] = c; bw[p + 1] = a; }
        }
        __syncwarp();
    }
    if (lane == 0) {
        float lut0 = g_lut[0];
        float corr = 0.f;
        int base = 0;
        int* oi = g_nzi + (size_t)row * EVCAP;
        float* ow = g_nzw + (size_t)row * EVCAP;
        int p = 0;
        while (p < n) {
            int j = bw[p];
            int m = 1;
            while (p + m < n && bw[p + m] == j) m++;
            float wgt = g_lut[m] - lut0;
            oi[base] = j;
            ow[base] = wgt;
            corr += wgt;
            base++;
            p += m;
        }
        g_nzc[row] = base;
        g_rowinv[row] = 1.0f / (1024.0f * lut0 + corr);
    }
}

// ---------------- output ----------------
__global__ __launch_bounds__(128) void out_kernel(float* __restrict__ out) {
    int row = blockIdx.x;
    int b = row >> 10;
    int e4 = threadIdx.x;
    float lut0 = g_lut[0];
    float4 us = ((const float4*)g_usum)[b * 128 + e4];
    float4 acc = make_float4(us.x * lut0, us.y * lut0, us.z * lut0, us.w * lut0);
    int n = g_nzc[row];
    const int* oi = g_nzi + (size_t)row * EVCAP;
    const float* ow = g_nzw + (size_t)row * EVCAP;
    const float4* ub = (const float4*)g_u + (size_t)b * LL * 128;
    for (int t = 0; t < n; t++) {
        int j = oi[t];
        float w = ow[t];
        float4 u4 = ub[(size_t)j * 128 + e4];
        acc.x += w * u4.x; acc.y += w * u4.y;
        acc.z += w * u4.z; acc.w += w * u4.w;
    }
    float inv = g_rowinv[row];
    float4 cc = ((const float4*)g_cvec)[e4];
    float4 o = make_float4(acc.x * inv + cc.x, acc.y * inv + cc.y,
                           acc.z * inv + cc.z, acc.w * inv + cc.w);
    ((float4*)out)[(size_t)row * 128 + e4] = o;
}

// ---------------- launch ----------------
extern "C" void kernel_launch(void* const* d_in, const int* in_sizes, int n_in,
                              void* d_out, int out_size) {
    const float* value = (const float*)d_in[2];
    const void*  tsq   = d_in[3];
    const void*  tsk   = d_in[4];
    const void*  ha    = d_in[5];
    const void*  hb    = d_in[6];
    const float* Wv    = (const float*)d_in[11];
    const float* bv    = (const float*)d_in[12];
    const float* Wo    = (const float*)d_in[13];
    const float* bo    = (const float*)d_in[14];
    float* out = (float*)d_out;

    init_kernel<<<17, 256>>>(ha);                                       // 0
    gemm_M2_kernel<<<dim3(8, 8, 4), 256>>>(Wo, Wv);                     // 1
    reduceM_kernel<<<EE * EE / 256, 256>>>();                           // 2
    gemm_u_kernel<<<dim3(BZ * LL / 128, EE / 128), 256>>>(value);       // 3 <- profiled
    sketch_kernel<<<2 * BZ * LL, 128>>>(tsq, tsk, ha, hb);              // 4
    sigT_kernel<<<dim3(KH / 32, LL / 32, 2 * BZ), dim3(32, 8)>>>();     // 5
    hashjoin_kernel<<<dim3(KH, BZ), 256>>>();                           // 6
    vsum1_kernel<<<dim3(16, BZ), 256>>>(value);                         // 7
    vsum2_kernel<<<dim3(EE / 128, BZ), 128>>>();                        // 8
    usum_kernel<<<dim3(EE / 8, BZ), 256>>>();                           // 9
    cvec_kernel<<<EE / 8, 256>>>(Wo, bv, bo);                           // 10
    build_sparse_kernel<<<BZ * LL / 8, 256>>>();                        // 11
    out_kernel<<<BZ * LL, 128>>>(out);                                  // 12
}